// round 13
// baseline (speedup 1.0000x reference)
#include <cuda_runtime.h>
#include <cstdint>

// x:      (2, 64, 32, 32, 32) fp32
// weight: (64, 32, 3, 3, 3)   fp32
// bias:   (32,)               fp32
// out:    (2, 32, 66, 66, 66) fp32
//
// Core: out[n,co,2z+1] = bias[co] + sum_{ci,tap} W[ci,co,26-tap]*x[n,ci,z-1+k]
// All other outputs bias-only. Conv CTAs write all of [0,64)^3 (2x2x2 cubes);
// prep kernel fills border slabs (any coord >= 64) + flips weights.

#define OUT_S 66
#define PLANE 4356            // 66*66
#define CH_STRIDE 287496      // 66^3
#define CIC 8
#define NCHUNK 8

// per-buffer smem: xs 8*6*10*10 floats = 19200 B, ws 8*27*32 = 27648 B
#define XS_BYTES 19200
#define BUF_BYTES 46848
#define SM_TOTAL (2 * BUF_BYTES)   // 93696 per CTA; 2 CTAs/SM = 187392

__device__ __align__(16) float g_wflip[64 * 27 * 32];

#define WPREP_BLOCKS 216
#define DHROW_BLOCKS 2080
#define WPAIR_BLOCKS 1024
#define PREP_BLOCKS (WPREP_BLOCKS + DHROW_BLOCKS + WPAIR_BLOCKS)

// ---------------------------------------------------------------------------
__global__ void prep_kernel(const float* __restrict__ w,
                            const float* __restrict__ bias,
                            float* __restrict__ out) {
    const int b   = blockIdx.x;
    const int tid = threadIdx.x;
    if (b < WPREP_BLOCKS) {
        int i = b * 256 + tid;
        if (i < 55296) {
            int ci = i / 864;
            int r  = i - ci * 864;
            int k  = r >> 5;
            int co = r & 31;
            g_wflip[i] = w[(ci * 32 + co) * 27 + (26 - k)];
        }
    } else if (b < WPREP_BLOCKS + DHROW_BLOCKS) {
        int wg   = (b - WPREP_BLOCKS) * 8 + (tid >> 5);
        int lane = tid & 31;
        int ch = wg / 260;
        int r  = wg - ch * 260;
        int d, h;
        if (r < 132) { d = 64 + (r >= 66 ? 1 : 0); h = r - (r >= 66 ? 66 : 0); }
        else         { int r2 = r - 132; d = r2 >> 1; h = 64 + (r2 & 1); }
        float bv = __ldg(&bias[ch & 31]);
        float* row = out + (size_t)ch * CH_STRIDE + (size_t)d * PLANE + h * OUT_S;
        for (int i = lane; i < OUT_S; i += 32) row[i] = bv;
    } else {
        int idx = (b - WPREP_BLOCKS - DHROW_BLOCKS) * 256 + tid;
        int ch  = idx >> 12;
        int rem = idx & 4095;
        int d   = rem >> 6;
        int h   = rem & 63;
        float bv = __ldg(&bias[ch & 31]);
        float2* p = (float2*)(out + (size_t)ch * CH_STRIDE
                              + (size_t)d * PLANE + h * OUT_S + 64);
        *p = make_float2(bv, bv);
    }
}

// ---------------------------------------------------------------------------
__device__ __forceinline__ void cp4_zfill(uint32_t saddr, const float* g, int ok) {
    asm volatile("cp.async.ca.shared.global [%0], [%1], 4, %2;"
                 :: "r"(saddr), "l"(g), "r"(ok ? 4 : 0) : "memory");
}
__device__ __forceinline__ void cp16(uint32_t saddr, const float4* g) {
    asm volatile("cp.async.cg.shared.global [%0], [%1], 16;"
                 :: "r"(saddr), "l"(g) : "memory");
}
__device__ __forceinline__ void cp_commit() {
    asm volatile("cp.async.commit_group;" ::: "memory");
}
template <int N>
__device__ __forceinline__ void cp_wait() {
    asm volatile("cp.async.wait_group %0;" :: "n"(N) : "memory");
}

// ---------------------------------------------------------------------------
// Block = 256 threads, (4,8,8) z-tile (d,h,w). Thread decode:
//   wq = tid&3, hq = (tid>>2)&3, dq = (tid>>4)&1   (lane bits)
//   cog = tid>>5 in [0,8)                           (warp-uniform)
// Thread owns a 2x2x2 point block at (zd0+2dq, zh0+2hq, zw0+2wq), 4 co
// (base cog*4). x halo per ci: [6][10][10]. Per ci: 4 halo d-planes of
// 16 x values (8 LDS.64 each, reused across taps), 54 broadcast LDS.128
// weights, 432 fma.rn.f32x2.
// Grid (4,4,16) = 256 CTAs, TWO per SM (independent phase overlap).
// cp.async double-buffered.
// ---------------------------------------------------------------------------
__global__ void __launch_bounds__(256, 2)
conv_core_kernel(const float* __restrict__ x,
                 const float* __restrict__ bias,
                 float* __restrict__ out) {
    extern __shared__ __align__(16) char smem[];
    uint32_t sb;
    asm("{ .reg .u64 t; cvta.to.shared.u64 t, %1; cvt.u32.u64 %0, t; }"
        : "=r"(sb) : "l"(smem));

    const int tid = threadIdx.x;
    const int wq  = tid & 3;
    const int hq  = (tid >> 2) & 3;
    const int dq  = (tid >> 4) & 1;
    const int cog = tid >> 5;                 // co base 4*cog

    const int tw = blockIdx.x, th = blockIdx.y;
    const int nz = blockIdx.z;                // 0..15
    const int n  = nz >> 3;
    const int td = nz & 7;
    const int zd0 = td * 4, zh0 = th * 8, zw0 = tw * 8;

    const float* xn = x + (size_t)n * (64 * 32768);

    auto issue_chunk = [&](int cc, int buf) {
        uint32_t sx = sb + buf * BUF_BYTES;
        // x halo: 8 ci x 6 x 10 x 10 = 4800 floats
#pragma unroll
        for (int j = 0; j < 19; ++j) {
            int i = tid + j * 256;
            if (i < 4800) {
                int ci = i / 600;
                int r  = i - ci * 600;
                int dd = r / 100;
                int r2 = r - dd * 100;
                int hh = r2 / 10;
                int ww = r2 - hh * 10;
                int gd = zd0 - 1 + dd;
                int gh = zh0 - 1 + hh;
                int gw = zw0 - 1 + ww;
                int ok = (gd >= 0 && gd < 32 && gh >= 0 && gh < 32 &&
                          gw >= 0 && gw < 32);
                const float* g = xn + (((size_t)(cc * CIC + ci) * 32 + (gd & 31))
                                       * 32 + (gh & 31)) * 32 + (gw & 31);
                cp4_zfill(sx + i * 4, g, ok);
            }
        }
        uint32_t sw = sx + XS_BYTES;
        const float4* gw4 = (const float4*)(g_wflip + cc * 6912);
#pragma unroll
        for (int j = 0; j < 7; ++j) {
            int i = tid + j * 256;
            if (i < 1728) cp16(sw + i * 16, gw4 + i);
        }
        cp_commit();
    };

    // acc[pd][ph][pw][j]: point (2dq+pd, 2hq+ph, 2wq+pw), co pair
    // {4cog+2j, 4cog+2j+1}
    unsigned long long acc[2][2][2][2];
#pragma unroll
    for (int a = 0; a < 2; ++a)
#pragma unroll
    for (int bq = 0; bq < 2; ++bq)
#pragma unroll
    for (int c = 0; c < 2; ++c)
#pragma unroll
    for (int e = 0; e < 2; ++e) acc[a][bq][c][e] = 0ull;

    issue_chunk(0, 0);

#pragma unroll 1
    for (int cc = 0; cc < NCHUNK; ++cc) {
        const int buf = cc & 1;
        if (cc + 1 < NCHUNK) {
            issue_chunk(cc + 1, buf ^ 1);
            cp_wait<1>();
        } else {
            cp_wait<0>();
        }
        __syncthreads();

        const float* xsb = (const float*)(smem + buf * BUF_BYTES);
        const float* wsb = (const float*)(smem + buf * BUF_BYTES + XS_BYTES);

#pragma unroll 1
        for (int ci = 0; ci < CIC; ++ci) {
            // patch base: dd = 2dq, hh = 2hq, ww = 2wq (halo coords)
            const float* xci = xsb + ci * 600 + dq * 200 + hq * 20 + wq * 2;
            const float* wb  = wsb + ci * 864 + cog * 4;

#pragma unroll
            for (int dz = 0; dz < 4; ++dz) {
                // ---- load one 4x4 halo plane: 8 LDS.64 -> 16 xv2 ----
                unsigned long long xv2[4][4];
#pragma unroll
                for (int hh = 0; hh < 4; ++hh) {
#pragma unroll
                    for (int wp = 0; wp < 2; ++wp) {
                        float2 f = *(const float2*)
                            (xci + dz * 100 + hh * 10 + wp * 2);
                        asm("mov.b64 %0, {%1, %1};"
                            : "=l"(xv2[hh][2 * wp])     : "f"(f.x));
                        asm("mov.b64 %0, {%1, %1};"
                            : "=l"(xv2[hh][2 * wp + 1]) : "f"(f.y));
                    }
                }
                // ---- taps feeding from this plane: pd + kd == dz ----
#pragma unroll
                for (int pd = 0; pd < 2; ++pd) {
                    const int kd = dz - pd;
                    if (kd < 0 || kd > 2) continue;
#pragma unroll
                    for (int kh = 0; kh < 3; ++kh) {
#pragma unroll
                        for (int kw = 0; kw < 3; ++kw) {
                            ulonglong2 wv = *(const ulonglong2*)
                                (wb + (kd * 9 + kh * 3 + kw) * 32);
#pragma unroll
                            for (int ph = 0; ph < 2; ++ph) {
#pragma unroll
                                for (int pw = 0; pw < 2; ++pw) {
                                    unsigned long long xv =
                                        xv2[ph + kh][pw + kw];
                                    asm("fma.rn.f32x2 %0, %1, %2, %0;"
                                        : "+l"(acc[pd][ph][pw][0])
                                        : "l"(xv), "l"(wv.x));
                                    asm("fma.rn.f32x2 %0, %1, %2, %0;"
                                        : "+l"(acc[pd][ph][pw][1])
                                        : "l"(xv), "l"(wv.y));
                                }
                            }
                        }
                    }
                }
            }
        }
        __syncthreads();
    }

    // ---- epilogue: full 2x2x2 output cubes per (point, co) ----
    float bv[4];
#pragma unroll
    for (int j = 0; j < 4; ++j) bv[j] = __ldg(&bias[cog * 4 + j]);

#pragma unroll
    for (int pd = 0; pd < 2; ++pd) {
        const int od = 2 * (zd0 + 2 * dq + pd);
#pragma unroll
        for (int ph = 0; ph < 2; ++ph) {
            const int ohe = 2 * (zh0 + 2 * hq + ph);
#pragma unroll
            for (int pw = 0; pw < 2; ++pw) {
                const int owe = 2 * (zw0 + 2 * wq + pw);
#pragma unroll
                for (int j = 0; j < 2; ++j) {
                    float2 v;
                    asm("mov.b64 {%0, %1}, %2;"
                        : "=f"(v.x), "=f"(v.y) : "l"(acc[pd][ph][pw][j]));
#pragma unroll
                    for (int s = 0; s < 2; ++s) {
                        const int co = cog * 4 + 2 * j + s;
                        const float b  = bv[2 * j + s];
                        const float cr = (s == 0 ? v.x : v.y) + b;
                        float* base = out
                            + (size_t)(n * 32 + co) * CH_STRIDE
                            + (size_t)od * PLANE + ohe * OUT_S + owe;
                        float2 bb = make_float2(b, b);
                        float2 bc = make_float2(b, cr);
                        *(float2*)(base)                 = bb;
                        *(float2*)(base + OUT_S)         = bb;
                        *(float2*)(base + PLANE)         = bb;
                        *(float2*)(base + PLANE + OUT_S) = bc;
                    }
                }
            }
        }
    }
}

// ---------------------------------------------------------------------------
extern "C" void kernel_launch(void* const* d_in, const int* in_sizes, int n_in,
                              void* d_out, int out_size) {
    const float* x = nullptr;
    const float* w = nullptr;
    const float* b = nullptr;
    for (int i = 0; i < n_in; ++i) {
        if (in_sizes[i] == 4194304)    x = (const float*)d_in[i];
        else if (in_sizes[i] == 55296) w = (const float*)d_in[i];
        else if (in_sizes[i] == 32)    b = (const float*)d_in[i];
    }
    float* out = (float*)d_out;

    cudaFuncSetAttribute(conv_core_kernel,
                         cudaFuncAttributeMaxDynamicSharedMemorySize, SM_TOTAL);

    prep_kernel<<<PREP_BLOCKS, 256>>>(w, b, out);

    dim3 grid(4, 4, 16);   // 256 CTAs = two per SM, phase overlap
    conv_core_kernel<<<grid, 256, SM_TOTAL>>>(x, b, out);
}

// round 14
// speedup vs baseline: 1.3432x; 1.3432x over previous
#include <cuda_runtime.h>
#include <cstdint>

// x:      (2, 64, 32, 32, 32) fp32
// weight: (64, 32, 3, 3, 3)   fp32
// bias:   (32,)               fp32
// out:    (2, 32, 66, 66, 66) fp32
//
// Core conv (32^3 grid): core[z] = sum_{ci,k} W'[ci,co,k] x[ci, z-1+k],
// W'[k] = W[26-k]. Scattered to all-odd output coords; rest bias-only.
// This kernel: Winograd F(2x2,3x3) in (h,w), direct sum over kd.
//   V = B^T d B   (input transform, per d-plane, per ci, per 4x4 tile)
//   U = G g G^T   (weight transform, precomputed)
//   M[zd] = sum_{kd,ci} V[zd+kd] * U[kd]   (elementwise in 16 pts)
//   Y = A^T M A   (output transform -> 2x2 outputs)

#define OUT_S 66
#define PLANE 4356
#define CH_STRIDE 287496
#define CIC 8
#define NCHUNK 8

// smem layout (bytes): x double-buffer, U double-buffer, V (reused as M)
#define X_BYTES 19200               // 8ci * 6*10*10 * 4
#define SM_U0   (2 * X_BYTES)       // 38400
#define U_BYTES 55296               // 3kd * 8ci * 16pt * 36 * 4
#define SM_V    (SM_U0 + 2 * U_BYTES)   // 148992
#define V_BYTES 49152               // 6dd * 8ci * 16pt * 16t * 4
#define SM_TOTAL (SM_V + V_BYTES)   // 198144

// Precomputed transformed weights: [kd][ci][pt][36] (co in [0,32), pad 4)
__device__ __align__(16) float g_U[3 * 64 * 16 * 36];

#define U_BLOCKS 24                 // 24*256 = 6144 = 3*64*32 units
#define DHROW_BLOCKS 2080
#define WPAIR_BLOCKS 1024
#define PREP_BLOCKS (U_BLOCKS + DHROW_BLOCKS + WPAIR_BLOCKS)

// ---------------------------------------------------------------------------
// prep: (a) weight transform U = G g G^T, (b) bias-fill border slabs.
// ---------------------------------------------------------------------------
__global__ void prep_kernel(const float* __restrict__ w,
                            const float* __restrict__ bias,
                            float* __restrict__ out) {
    const int b   = blockIdx.x;
    const int tid = threadIdx.x;
    if (b < U_BLOCKS) {
        int i = b * 256 + tid;                  // (kd, ci, co)
        int kd = i >> 11;
        int r  = i & 2047;
        int ci = r >> 5;
        int co = r & 31;
        float g[3][3];
#pragma unroll
        for (int kh = 0; kh < 3; ++kh)
#pragma unroll
            for (int kw = 0; kw < 3; ++kw)
                g[kh][kw] = w[(ci * 32 + co) * 27
                              + (26 - (kd * 9 + kh * 3 + kw))];
        float tg[3][4];
#pragma unroll
        for (int kh = 0; kh < 3; ++kh) {
            tg[kh][0] = g[kh][0];
            tg[kh][1] = 0.5f * (g[kh][0] + g[kh][1] + g[kh][2]);
            tg[kh][2] = 0.5f * (g[kh][0] - g[kh][1] + g[kh][2]);
            tg[kh][3] = g[kh][2];
        }
        float* dst = g_U + ((kd * 64 + ci) * 16) * 36 + co;
#pragma unroll
        for (int q = 0; q < 4; ++q) {
            float u0 = tg[0][q];
            float u1 = 0.5f * (tg[0][q] + tg[1][q] + tg[2][q]);
            float u2 = 0.5f * (tg[0][q] - tg[1][q] + tg[2][q]);
            float u3 = tg[2][q];
            dst[(0 * 4 + q) * 36] = u0;
            dst[(1 * 4 + q) * 36] = u1;
            dst[(2 * 4 + q) * 36] = u2;
            dst[(3 * 4 + q) * 36] = u3;
        }
    } else if (b < U_BLOCKS + DHROW_BLOCKS) {
        int wg   = (b - U_BLOCKS) * 8 + (tid >> 5);
        int lane = tid & 31;
        int ch = wg / 260;
        int r  = wg - ch * 260;
        int d, h;
        if (r < 132) { d = 64 + (r >= 66 ? 1 : 0); h = r - (r >= 66 ? 66 : 0); }
        else         { int r2 = r - 132; d = r2 >> 1; h = 64 + (r2 & 1); }
        float bv = __ldg(&bias[ch & 31]);
        float* row = out + (size_t)ch * CH_STRIDE + (size_t)d * PLANE + h * OUT_S;
        for (int i = lane; i < OUT_S; i += 32) row[i] = bv;
    } else {
        int idx = (b - U_BLOCKS - DHROW_BLOCKS) * 256 + tid;
        int ch  = idx >> 12;
        int rem = idx & 4095;
        int d   = rem >> 6;
        int h   = rem & 63;
        float bv = __ldg(&bias[ch & 31]);
        float2* p = (float2*)(out + (size_t)ch * CH_STRIDE
                              + (size_t)d * PLANE + h * OUT_S + 64);
        *p = make_float2(bv, bv);
    }
}

// ---------------------------------------------------------------------------
__device__ __forceinline__ void cp4_zfill(uint32_t saddr, const float* g, int ok) {
    asm volatile("cp.async.ca.shared.global [%0], [%1], 4, %2;"
                 :: "r"(saddr), "l"(g), "r"(ok ? 4 : 0) : "memory");
}
__device__ __forceinline__ void cp16(uint32_t saddr, const float4* g) {
    asm volatile("cp.async.cg.shared.global [%0], [%1], 16;"
                 :: "r"(saddr), "l"(g) : "memory");
}
__device__ __forceinline__ void cp_commit() {
    asm volatile("cp.async.commit_group;" ::: "memory");
}
template <int N>
__device__ __forceinline__ void cp_wait() {
    asm volatile("cp.async.wait_group %0;" :: "n"(N) : "memory");
}

// ---------------------------------------------------------------------------
// Block = 512 threads. CTA tile: 4 zd x 8 h x 8 w outputs (z coords).
// Multiply-stage thread decode: tp = tid&7 (tile pair -> tiles 2tp,2tp+1),
// pt = (tid>>3)&15 (Winograd point), cog = tid>>7 (co octet base 8*cog).
// M accumulators: acc[zd 4][tile e 2][co-pair 4] f32x2.
// Grid (4,4,16) = 256 CTAs (2 waves).
// ---------------------------------------------------------------------------
__global__ void __launch_bounds__(512, 1)
conv_wino_kernel(const float* __restrict__ x,
                 const float* __restrict__ bias,
                 float* __restrict__ out) {
    extern __shared__ __align__(16) char smem[];
    uint32_t sb;
    asm("{ .reg .u64 t; cvta.to.shared.u64 t, %1; cvt.u32.u64 %0, t; }"
        : "=r"(sb) : "l"(smem));

    const int tid = threadIdx.x;
    const int tp  = tid & 7;
    const int pt  = (tid >> 3) & 15;
    const int cog = tid >> 7;                 // 0..3

    const int tw = blockIdx.x, th = blockIdx.y;
    const int nz = blockIdx.z;                // 0..15
    const int n  = nz >> 3;
    const int td = nz & 7;
    const int zd0 = td * 4, zh0 = th * 8, zw0 = tw * 8;

    const float* xn = x + (size_t)n * (64 * 32768);
    float* Vs = (float*)(smem + SM_V);

    auto issue_chunk = [&](int cc, int buf) {
        // x halo: 8ci x [6][10][10]
        uint32_t sx = sb + buf * X_BYTES;
#pragma unroll
        for (int j = 0; j < 10; ++j) {
            int i = tid + j * 512;
            if (i < 4800) {
                int ci = i / 600;
                int r  = i - ci * 600;
                int dd = r / 100;
                int r2 = r - dd * 100;
                int hh = r2 / 10;
                int ww = r2 - hh * 10;
                int gd = zd0 - 1 + dd;
                int gh = zh0 - 1 + hh;
                int gw = zw0 - 1 + ww;
                int ok = (gd >= 0 && gd < 32 && gh >= 0 && gh < 32 &&
                          gw >= 0 && gw < 32);
                const float* g = xn + (((size_t)(cc * CIC + ci) * 32 + (gd & 31))
                                       * 32 + (gh & 31)) * 32 + (gw & 31);
                cp4_zfill(sx + i * 4, g, ok);
            }
        }
        // U chunk: per kd, 8ci x 16pt x 36 floats (contiguous per kd)
        uint32_t su = sb + SM_U0 + buf * U_BYTES;
#pragma unroll
        for (int j = 0; j < 7; ++j) {
            int i = tid + j * 512;              // float4 index, total 3456
            if (i < 3456) {
                int kd = i / 1152;
                int r  = i - kd * 1152;
                const float4* src = (const float4*)
                    (g_U + (kd * 64 + cc * CIC) * (16 * 36)) + r;
                cp16(su + (kd * 1152 + r) * 16, src);
            }
        }
        cp_commit();
    };

    // acc[zd][e][j]: tile 2tp+e, co pair {8cog+2j, 8cog+2j+1}
    unsigned long long acc[4][2][4];
#pragma unroll
    for (int a = 0; a < 4; ++a)
#pragma unroll
    for (int e = 0; e < 2; ++e)
#pragma unroll
    for (int j = 0; j < 4; ++j) acc[a][e][j] = 0ull;

    issue_chunk(0, 0);

#pragma unroll 1
    for (int cc = 0; cc < NCHUNK; ++cc) {
        const int buf = cc & 1;
        if (cc + 1 < NCHUNK) {
            issue_chunk(cc + 1, buf ^ 1);
            cp_wait<1>();
        } else {
            cp_wait<0>();
        }
        __syncthreads();   // x/U ready; prev multiply done (V reusable)

        // ---- build V = B^T d B : 768 units (dd 6, ci 8, tile 16) ----
        {
            const float* xb = (const float*)(smem + buf * X_BYTES);
#pragma unroll
            for (int u = tid; u < 768; u += 512) {
                int t  = u & 15;
                int ci = (u >> 4) & 7;
                int dd = u >> 7;
                int a  = t >> 2, b2 = t & 3;
                const float* dp = xb + ci * 600 + dd * 100 + (2 * a) * 10 + 2 * b2;
                float rt[4][4];
#pragma unroll
                for (int i = 0; i < 4; ++i) {
                    float d0 = dp[i * 10 + 0], d1 = dp[i * 10 + 1];
                    float d2 = dp[i * 10 + 2], d3 = dp[i * 10 + 3];
                    rt[i][0] = d0 - d2;
                    rt[i][1] = d1 + d2;
                    rt[i][2] = d2 - d1;
                    rt[i][3] = d1 - d3;
                }
                float* vd = Vs + ((dd * 8 + ci) * 16) * 16 + t;
#pragma unroll
                for (int q = 0; q < 4; ++q) {
                    vd[(0 * 4 + q) * 16] = rt[0][q] - rt[2][q];
                    vd[(1 * 4 + q) * 16] = rt[1][q] + rt[2][q];
                    vd[(2 * 4 + q) * 16] = rt[2][q] - rt[1][q];
                    vd[(3 * 4 + q) * 16] = rt[1][q] - rt[3][q];
                }
            }
        }
        __syncthreads();

        // ---- multiply: M[zd] += V[zd+kd] * U[kd], elementwise in pt ----
        {
            const float* Ub = (const float*)(smem + SM_U0 + buf * U_BYTES);
#pragma unroll 1
            for (int ci = 0; ci < CIC; ++ci) {
                unsigned long long xv[6][2];
#pragma unroll
                for (int dd = 0; dd < 6; ++dd) {
                    float2 f = *(const float2*)
                        (Vs + ((dd * 8 + ci) * 16 + pt) * 16 + 2 * tp);
                    asm("mov.b64 %0, {%1, %1};" : "=l"(xv[dd][0]) : "f"(f.x));
                    asm("mov.b64 %0, {%1, %1};" : "=l"(xv[dd][1]) : "f"(f.y));
                }
#pragma unroll
                for (int kd = 0; kd < 3; ++kd) {
                    const float* up = Ub + ((kd * 8 + ci) * 16 + pt) * 36
                                    + 8 * cog;
                    ulonglong2 w0 = *(const ulonglong2*)up;
                    ulonglong2 w1 = *(const ulonglong2*)(up + 4);
#pragma unroll
                    for (int zd = 0; zd < 4; ++zd) {
#pragma unroll
                        for (int e = 0; e < 2; ++e) {
                            unsigned long long xvv = xv[zd + kd][e];
                            asm("fma.rn.f32x2 %0, %1, %2, %0;"
                                : "+l"(acc[zd][e][0]) : "l"(xvv), "l"(w0.x));
                            asm("fma.rn.f32x2 %0, %1, %2, %0;"
                                : "+l"(acc[zd][e][1]) : "l"(xvv), "l"(w0.y));
                            asm("fma.rn.f32x2 %0, %1, %2, %0;"
                                : "+l"(acc[zd][e][2]) : "l"(xvv), "l"(w1.x));
                            asm("fma.rn.f32x2 %0, %1, %2, %0;"
                                : "+l"(acc[zd][e][3]) : "l"(xvv), "l"(w1.y));
                        }
                    }
                }
            }
        }
        __syncthreads();   // multiply done before V (or M staging) overwrite
    }

    // ---- output: per zd: stage M -> smem, transform Y = A^T M A, store ----
    float* Msm = Vs;                       // [pt][33 co][16 t]
    const int t2  = tid & 15;              // tile for transform stage
    const int co2 = tid >> 4;              // 0..31
    const float bvv = __ldg(&bias[co2]);
    const int a2 = t2 >> 2, b2 = t2 & 3;

#pragma unroll 1
    for (int zd = 0; zd < 4; ++zd) {
        // stage M[zd]
#pragma unroll
        for (int e = 0; e < 2; ++e) {
#pragma unroll
            for (int j = 0; j < 4; ++j) {
                float2 v;
                asm("mov.b64 {%0, %1}, %2;"
                    : "=f"(v.x), "=f"(v.y) : "l"(acc[zd][e][j]));
                int co = 8 * cog + 2 * j;
                int t  = 2 * tp + e;
                Msm[(pt * 33 + co)     * 16 + t] = v.x;
                Msm[(pt * 33 + co + 1) * 16 + t] = v.y;
            }
        }
        __syncthreads();

        // transform: thread (t2, co2)
        float m[16];
#pragma unroll
        for (int p = 0; p < 16; ++p)
            m[p] = Msm[(p * 33 + co2) * 16 + t2];
        float tq0[4], tq1[4];
#pragma unroll
        for (int p = 0; p < 4; ++p) {
            tq0[p] = m[4 * p] + m[4 * p + 1] + m[4 * p + 2];
            tq1[p] = m[4 * p + 1] - m[4 * p + 2] - m[4 * p + 3];
        }
        float Y[2][2];
        Y[0][0] = tq0[0] + tq0[1] + tq0[2];
        Y[0][1] = tq1[0] + tq1[1] + tq1[2];
        Y[1][0] = tq0[1] - tq0[2] - tq0[3];
        Y[1][1] = tq1[1] - tq1[2] - tq1[3];

        // write 2x2x2 cubes for the 2x2 (h,w) outputs of this tile at zd
        const int zg = zd0 + zd;
#pragma unroll
        for (int i = 0; i < 2; ++i) {
#pragma unroll
            for (int j = 0; j < 2; ++j) {
                const int hg = zh0 + 2 * a2 + i;
                const int wg = zw0 + 2 * b2 + j;
                float* base = out + (size_t)(n * 32 + co2) * CH_STRIDE
                            + (size_t)(2 * zg) * PLANE
                            + (2 * hg) * OUT_S + 2 * wg;
                float2 bb = make_float2(bvv, bvv);
                float2 bc = make_float2(bvv, Y[i][j] + bvv);
                *(float2*)(base)                 = bb;
                *(float2*)(base + OUT_S)         = bb;
                *(float2*)(base + PLANE)         = bb;
                *(float2*)(base + PLANE + OUT_S) = bc;
            }
        }
        __syncthreads();   // before next zd overwrites Msm
    }
}

// ---------------------------------------------------------------------------
extern "C" void kernel_launch(void* const* d_in, const int* in_sizes, int n_in,
                              void* d_out, int out_size) {
    const float* x = nullptr;
    const float* w = nullptr;
    const float* b = nullptr;
    for (int i = 0; i < n_in; ++i) {
        if (in_sizes[i] == 4194304)    x = (const float*)d_in[i];
        else if (in_sizes[i] == 55296) w = (const float*)d_in[i];
        else if (in_sizes[i] == 32)    b = (const float*)d_in[i];
    }
    float* out = (float*)d_out;

    cudaFuncSetAttribute(conv_wino_kernel,
                         cudaFuncAttributeMaxDynamicSharedMemorySize, SM_TOTAL);

    prep_kernel<<<PREP_BLOCKS, 256>>>(w, b, out);

    dim3 grid(4, 4, 16);   // 256 CTAs, 2 waves
    conv_wino_kernel<<<grid, 512, SM_TOTAL>>>(x, b, out);
}

// round 15
// speedup vs baseline: 1.3444x; 1.0009x over previous
#include <cuda_runtime.h>
#include <cstdint>

// x:      (2, 64, 32, 32, 32) fp32
// weight: (64, 32, 3, 3, 3)   fp32
// bias:   (32,)               fp32
// out:    (2, 32, 66, 66, 66) fp32
//
// Winograd F(2x2,3x3) in (h,w), direct sum over kd (see R14).
// This round: 256-thread CTAs, CIC=4, 83.7KB smem -> 2 co-resident CTAs/SM.

#define OUT_S 66
#define PLANE 4356
#define CH_STRIDE 287496
#define CIC 4
#define NCHUNK 16

// smem layout (bytes)
#define X_BYTES 5760                // 4ci * 6*10*6 * 4
#define SM_U0   (2 * X_BYTES)       // 11520
#define U_BYTES 27648               // 3kd * 4ci * 16pt * 36 * 4
#define SM_V    (SM_U0 + 2 * U_BYTES)   // 66816
#define MSM_BYTES 16896             // 16pt * 33co * 8t * 4 (>= V 13056)
#define SM_TOTAL (SM_V + MSM_BYTES) // 83712

// V layout: word index = (dd*4+ci)*136 + pt*8 + t   (ci stride 136 = 8 mod 32)
#define VCI 136

// Precomputed transformed weights: [kd][ci][pt][36] (co in [0,32), pad 4)
__device__ __align__(16) float g_U[3 * 64 * 16 * 36];

#define U_BLOCKS 24
#define DHROW_BLOCKS 2080
#define WPAIR_BLOCKS 1024
#define PREP_BLOCKS (U_BLOCKS + DHROW_BLOCKS + WPAIR_BLOCKS)

// ---------------------------------------------------------------------------
__global__ void prep_kernel(const float* __restrict__ w,
                            const float* __restrict__ bias,
                            float* __restrict__ out) {
    const int b   = blockIdx.x;
    const int tid = threadIdx.x;
    if (b < U_BLOCKS) {
        int i = b * 256 + tid;
        int kd = i >> 11;
        int r  = i & 2047;
        int ci = r >> 5;
        int co = r & 31;
        float g[3][3];
#pragma unroll
        for (int kh = 0; kh < 3; ++kh)
#pragma unroll
            for (int kw = 0; kw < 3; ++kw)
                g[kh][kw] = w[(ci * 32 + co) * 27
                              + (26 - (kd * 9 + kh * 3 + kw))];
        float tg[3][4];
#pragma unroll
        for (int kh = 0; kh < 3; ++kh) {
            tg[kh][0] = g[kh][0];
            tg[kh][1] = 0.5f * (g[kh][0] + g[kh][1] + g[kh][2]);
            tg[kh][2] = 0.5f * (g[kh][0] - g[kh][1] + g[kh][2]);
            tg[kh][3] = g[kh][2];
        }
        float* dst = g_U + ((kd * 64 + ci) * 16) * 36 + co;
#pragma unroll
        for (int q = 0; q < 4; ++q) {
            dst[(0 * 4 + q) * 36] = tg[0][q];
            dst[(1 * 4 + q) * 36] = 0.5f * (tg[0][q] + tg[1][q] + tg[2][q]);
            dst[(2 * 4 + q) * 36] = 0.5f * (tg[0][q] - tg[1][q] + tg[2][q]);
            dst[(3 * 4 + q) * 36] = tg[2][q];
        }
    } else if (b < U_BLOCKS + DHROW_BLOCKS) {
        int wg   = (b - U_BLOCKS) * 8 + (tid >> 5);
        int lane = tid & 31;
        int ch = wg / 260;
        int r  = wg - ch * 260;
        int d, h;
        if (r < 132) { d = 64 + (r >= 66 ? 1 : 0); h = r - (r >= 66 ? 66 : 0); }
        else         { int r2 = r - 132; d = r2 >> 1; h = 64 + (r2 & 1); }
        float bv = __ldg(&bias[ch & 31]);
        float* row = out + (size_t)ch * CH_STRIDE + (size_t)d * PLANE + h * OUT_S;
        for (int i = lane; i < OUT_S; i += 32) row[i] = bv;
    } else {
        int idx = (b - U_BLOCKS - DHROW_BLOCKS) * 256 + tid;
        int ch  = idx >> 12;
        int rem = idx & 4095;
        int d   = rem >> 6;
        int h   = rem & 63;
        float bv = __ldg(&bias[ch & 31]);
        float2* p = (float2*)(out + (size_t)ch * CH_STRIDE
                              + (size_t)d * PLANE + h * OUT_S + 64);
        *p = make_float2(bv, bv);
    }
}

// ---------------------------------------------------------------------------
__device__ __forceinline__ void cp4_zfill(uint32_t saddr, const float* g, int ok) {
    asm volatile("cp.async.ca.shared.global [%0], [%1], 4, %2;"
                 :: "r"(saddr), "l"(g), "r"(ok ? 4 : 0) : "memory");
}
__device__ __forceinline__ void cp16(uint32_t saddr, const float4* g) {
    asm volatile("cp.async.cg.shared.global [%0], [%1], 16;"
                 :: "r"(saddr), "l"(g) : "memory");
}
__device__ __forceinline__ void cp_commit() {
    asm volatile("cp.async.commit_group;" ::: "memory");
}
template <int N>
__device__ __forceinline__ void cp_wait() {
    asm volatile("cp.async.wait_group %0;" :: "n"(N) : "memory");
}

// ---------------------------------------------------------------------------
// Block = 256 threads. CTA tile: 4 zd x 8 h x 4 w (z coords) = 8 hw-tiles.
// Multiply decode: tp = tid&3 (tile pair -> t = 2tp+e), cog = (tid>>2)&3
// (co base 8*cog), pt = tid>>4 (Winograd point; 2 pts per warp).
// acc[zd 4][e 2][co-pair 4] f32x2 = 32 regs.
// Grid (8,4,16) = 512 CTAs; __launch_bounds__(256,2) -> 2 CTAs/SM co-resident.
// ---------------------------------------------------------------------------
__global__ void __launch_bounds__(256, 2)
conv_wino_kernel(const float* __restrict__ x,
                 const float* __restrict__ bias,
                 float* __restrict__ out) {
    extern __shared__ __align__(16) char smem[];
    uint32_t sb;
    asm("{ .reg .u64 t; cvta.to.shared.u64 t, %1; cvt.u32.u64 %0, t; }"
        : "=r"(sb) : "l"(smem));

    const int tid = threadIdx.x;
    const int tp  = tid & 3;
    const int cog = (tid >> 2) & 3;
    const int pt  = tid >> 4;                 // 0..15

    const int tw = blockIdx.x;                // 0..7 (w-tile of 4)
    const int th = blockIdx.y;                // 0..3 (h-tile of 8)
    const int nz = blockIdx.z;                // 0..15
    const int n  = nz >> 3;
    const int td = nz & 7;
    const int zd0 = td * 4, zh0 = th * 8, zw0 = tw * 4;

    const float* xn = x + (size_t)n * (64 * 32768);
    float* Vs = (float*)(smem + SM_V);

    auto issue_chunk = [&](int cc, int buf) {
        // x halo: 4ci x [6][10][6] = 1440 floats
        uint32_t sx = sb + buf * X_BYTES;
#pragma unroll
        for (int j = 0; j < 6; ++j) {
            int i = tid + j * 256;
            if (i < 1440) {
                int ci = i / 360;
                int r  = i - ci * 360;
                int dd = r / 60;
                int r2 = r - dd * 60;
                int hh = r2 / 6;
                int ww = r2 - hh * 6;
                int gd = zd0 - 1 + dd;
                int gh = zh0 - 1 + hh;
                int gw = zw0 - 1 + ww;
                int ok = (gd >= 0 && gd < 32 && gh >= 0 && gh < 32 &&
                          gw >= 0 && gw < 32);
                const float* g = xn + (((size_t)(cc * CIC + ci) * 32 + (gd & 31))
                                       * 32 + (gh & 31)) * 32 + (gw & 31);
                cp4_zfill(sx + i * 4, g, ok);
            }
        }
        // U chunk: 3kd x 4ci x 16pt x 36 = 1728 float4
        uint32_t su = sb + SM_U0 + buf * U_BYTES;
#pragma unroll
        for (int j = 0; j < 7; ++j) {
            int i = tid + j * 256;
            if (i < 1728) {
                int kd = i / 576;
                int r  = i - kd * 576;
                const float4* src = (const float4*)
                    (g_U + (kd * 64 + cc * CIC) * (16 * 36)) + r;
                cp16(su + (kd * 576 + r) * 16, src);
            }
        }
        cp_commit();
    };

    // acc[zd][e][j]: tile 2tp+e, co pair {8cog+2j, 8cog+2j+1}
    unsigned long long acc[4][2][4];
#pragma unroll
    for (int a = 0; a < 4; ++a)
#pragma unroll
    for (int e = 0; e < 2; ++e)
#pragma unroll
    for (int j = 0; j < 4; ++j) acc[a][e][j] = 0ull;

    issue_chunk(0, 0);

#pragma unroll 1
    for (int cc = 0; cc < NCHUNK; ++cc) {
        const int buf = cc & 1;
        if (cc + 1 < NCHUNK) {
            issue_chunk(cc + 1, buf ^ 1);
            cp_wait<1>();
        } else {
            cp_wait<0>();
        }
        __syncthreads();

        // ---- build V = B^T d B : 192 units (dd 6, ci 4, tile 8) ----
        if (tid < 192) {
            int t  = tid & 7;                 // t = a*2 + b
            int ci = (tid >> 3) & 3;
            int dd = tid >> 5;
            int a  = t >> 1, b2 = t & 1;
            const float* dp = (const float*)(smem + buf * X_BYTES)
                            + ci * 360 + dd * 60 + (2 * a) * 6 + 2 * b2;
            float rt[4][4];
#pragma unroll
            for (int i = 0; i < 4; ++i) {
                float d0 = dp[i * 6 + 0], d1 = dp[i * 6 + 1];
                float d2 = dp[i * 6 + 2], d3 = dp[i * 6 + 3];
                rt[i][0] = d0 - d2;
                rt[i][1] = d1 + d2;
                rt[i][2] = d2 - d1;
                rt[i][3] = d1 - d3;
            }
            float* vd = Vs + (dd * 4 + ci) * VCI + t;
#pragma unroll
            for (int q = 0; q < 4; ++q) {
                vd[(0 * 4 + q) * 8] = rt[0][q] - rt[2][q];
                vd[(1 * 4 + q) * 8] = rt[1][q] + rt[2][q];
                vd[(2 * 4 + q) * 8] = rt[2][q] - rt[1][q];
                vd[(3 * 4 + q) * 8] = rt[1][q] - rt[3][q];
            }
        }
        __syncthreads();

        // ---- multiply: M[zd] += V[zd+kd] * U[kd] ----
        {
            const float* Ub = (const float*)(smem + SM_U0 + buf * U_BYTES);
#pragma unroll 1
            for (int ci = 0; ci < CIC; ++ci) {
                unsigned long long xv[6][2];
#pragma unroll
                for (int dd = 0; dd < 6; ++dd) {
                    float2 f = *(const float2*)
                        (Vs + (dd * 4 + ci) * VCI + pt * 8 + 2 * tp);
                    asm("mov.b64 %0, {%1, %1};" : "=l"(xv[dd][0]) : "f"(f.x));
                    asm("mov.b64 %0, {%1, %1};" : "=l"(xv[dd][1]) : "f"(f.y));
                }
#pragma unroll
                for (int kd = 0; kd < 3; ++kd) {
                    const float* up = Ub + ((kd * 4 + ci) * 16 + pt) * 36
                                    + 8 * cog;
                    ulonglong2 w0 = *(const ulonglong2*)up;
                    ulonglong2 w1 = *(const ulonglong2*)(up + 4);
#pragma unroll
                    for (int zd = 0; zd < 4; ++zd) {
#pragma unroll
                        for (int e = 0; e < 2; ++e) {
                            unsigned long long xvv = xv[zd + kd][e];
                            asm("fma.rn.f32x2 %0, %1, %2, %0;"
                                : "+l"(acc[zd][e][0]) : "l"(xvv), "l"(w0.x));
                            asm("fma.rn.f32x2 %0, %1, %2, %0;"
                                : "+l"(acc[zd][e][1]) : "l"(xvv), "l"(w0.y));
                            asm("fma.rn.f32x2 %0, %1, %2, %0;"
                                : "+l"(acc[zd][e][2]) : "l"(xvv), "l"(w1.x));
                            asm("fma.rn.f32x2 %0, %1, %2, %0;"
                                : "+l"(acc[zd][e][3]) : "l"(xvv), "l"(w1.y));
                        }
                    }
                }
            }
        }
        __syncthreads();
    }

    // ---- output: per zd: stage M, transform Y = A^T M A, store cubes ----
    float* Msm = Vs;                       // [pt][33 co][8 t]
    const int t2  = tid & 7;
    const int co2 = (tid >> 3) & 31;
    const float bvv = __ldg(&bias[co2]);
    const int a2 = t2 >> 1, b2 = t2 & 1;

#pragma unroll 1
    for (int zd = 0; zd < 4; ++zd) {
#pragma unroll
        for (int e = 0; e < 2; ++e) {
#pragma unroll
            for (int j = 0; j < 4; ++j) {
                float2 v;
                asm("mov.b64 {%0, %1}, %2;"
                    : "=f"(v.x), "=f"(v.y) : "l"(acc[zd][e][j]));
                int co = 8 * cog + 2 * j;
                int t  = 2 * tp + e;
                Msm[(pt * 33 + co)     * 8 + t] = v.x;
                Msm[(pt * 33 + co + 1) * 8 + t] = v.y;
            }
        }
        __syncthreads();

        float m[16];
#pragma unroll
        for (int p = 0; p < 16; ++p)
            m[p] = Msm[(p * 33 + co2) * 8 + t2];
        float tq0[4], tq1[4];
#pragma unroll
        for (int p = 0; p < 4; ++p) {
            tq0[p] = m[4 * p] + m[4 * p + 1] + m[4 * p + 2];
            tq1[p] = m[4 * p + 1] - m[4 * p + 2] - m[4 * p + 3];
        }
        float Y[2][2];
        Y[0][0] = tq0[0] + tq0[1] + tq0[2];
        Y[0][1] = tq1[0] + tq1[1] + tq1[2];
        Y[1][0] = tq0[1] - tq0[2] - tq0[3];
        Y[1][1] = tq1[1] - tq1[2] - tq1[3];

        const int zg = zd0 + zd;
#pragma unroll
        for (int i = 0; i < 2; ++i) {
#pragma unroll
            for (int j = 0; j < 2; ++j) {
                const int hg = zh0 + 2 * a2 + i;
                const int wg = zw0 + 2 * b2 + j;
                float* base = out + (size_t)(n * 32 + co2) * CH_STRIDE
                            + (size_t)(2 * zg) * PLANE
                            + (2 * hg) * OUT_S + 2 * wg;
                float2 bb = make_float2(bvv, bvv);
                float2 bc = make_float2(bvv, Y[i][j] + bvv);
                *(float2*)(base)                 = bb;
                *(float2*)(base + OUT_S)         = bb;
                *(float2*)(base + PLANE)         = bb;
                *(float2*)(base + PLANE + OUT_S) = bc;
            }
        }
        __syncthreads();
    }
}

// ---------------------------------------------------------------------------
extern "C" void kernel_launch(void* const* d_in, const int* in_sizes, int n_in,
                              void* d_out, int out_size) {
    const float* x = nullptr;
    const float* w = nullptr;
    const float* b = nullptr;
    for (int i = 0; i < n_in; ++i) {
        if (in_sizes[i] == 4194304)    x = (const float*)d_in[i];
        else if (in_sizes[i] == 55296) w = (const float*)d_in[i];
        else if (in_sizes[i] == 32)    b = (const float*)d_in[i];
    }
    float* out = (float*)d_out;

    cudaFuncSetAttribute(conv_wino_kernel,
                         cudaFuncAttributeMaxDynamicSharedMemorySize, SM_TOTAL);

    prep_kernel<<<PREP_BLOCKS, 256>>>(w, b, out);

    dim3 grid(8, 4, 16);   // 512 CTAs, 2 co-resident per SM
    conv_wino_kernel<<<grid, 256, SM_TOTAL>>>(x, b, out);
}

// round 16
// speedup vs baseline: 1.3689x; 1.0182x over previous
#include <cuda_runtime.h>
#include <cstdint>

// x:      (2, 64, 32, 32, 32) fp32
// weight: (64, 32, 3, 3, 3)   fp32
// bias:   (32,)               fp32
// out:    (2, 32, 66, 66, 66) fp32
//
// Winograd F(2x2,3x3) in (h,w), direct sum over kd.
// This round: CTA tile 2zd x 8h x 4w -> acc halved (32 regs) so ptxas can
// software-pipeline the V/U shared loads. 1024 CTAs, 2 co-resident per SM.

#define OUT_S 66
#define PLANE 4356
#define CH_STRIDE 287496
#define CIC 4
#define NCHUNK 16

// smem layout (bytes)
#define X_BYTES 3840                // 4ci * 4dd*10*6 * 4
#define SM_U0   (2 * X_BYTES)       // 7680
#define U_BYTES 27648               // 3kd * 4ci * 16pt * 36 * 4
#define SM_V    (SM_U0 + 2 * U_BYTES)   // 62976
#define MSM_BYTES 16896             // 16pt * 33co * 8t * 4 (>= V 8704)
#define SM_TOTAL (SM_V + MSM_BYTES) // 79872

// V layout: word index = (dd*4+ci)*136 + pt*8 + t
#define VCI 136

// Precomputed transformed weights: [kd][ci][pt][36] (co in [0,32), pad 4)
__device__ __align__(16) float g_U[3 * 64 * 16 * 36];

#define U_BLOCKS 24
#define DHROW_BLOCKS 2080
#define WPAIR_BLOCKS 1024
#define PREP_BLOCKS (U_BLOCKS + DHROW_BLOCKS + WPAIR_BLOCKS)

// ---------------------------------------------------------------------------
__global__ void prep_kernel(const float* __restrict__ w,
                            const float* __restrict__ bias,
                            float* __restrict__ out) {
    const int b   = blockIdx.x;
    const int tid = threadIdx.x;
    if (b < U_BLOCKS) {
        int i = b * 256 + tid;
        int kd = i >> 11;
        int r  = i & 2047;
        int ci = r >> 5;
        int co = r & 31;
        float g[3][3];
#pragma unroll
        for (int kh = 0; kh < 3; ++kh)
#pragma unroll
            for (int kw = 0; kw < 3; ++kw)
                g[kh][kw] = w[(ci * 32 + co) * 27
                              + (26 - (kd * 9 + kh * 3 + kw))];
        float tg[3][4];
#pragma unroll
        for (int kh = 0; kh < 3; ++kh) {
            tg[kh][0] = g[kh][0];
            tg[kh][1] = 0.5f * (g[kh][0] + g[kh][1] + g[kh][2]);
            tg[kh][2] = 0.5f * (g[kh][0] - g[kh][1] + g[kh][2]);
            tg[kh][3] = g[kh][2];
        }
        float* dst = g_U + ((kd * 64 + ci) * 16) * 36 + co;
#pragma unroll
        for (int q = 0; q < 4; ++q) {
            dst[(0 * 4 + q) * 36] = tg[0][q];
            dst[(1 * 4 + q) * 36] = 0.5f * (tg[0][q] + tg[1][q] + tg[2][q]);
            dst[(2 * 4 + q) * 36] = 0.5f * (tg[0][q] - tg[1][q] + tg[2][q]);
            dst[(3 * 4 + q) * 36] = tg[2][q];
        }
    } else if (b < U_BLOCKS + DHROW_BLOCKS) {
        int wg   = (b - U_BLOCKS) * 8 + (tid >> 5);
        int lane = tid & 31;
        int ch = wg / 260;
        int r  = wg - ch * 260;
        int d, h;
        if (r < 132) { d = 64 + (r >= 66 ? 1 : 0); h = r - (r >= 66 ? 66 : 0); }
        else         { int r2 = r - 132; d = r2 >> 1; h = 64 + (r2 & 1); }
        float bv = __ldg(&bias[ch & 31]);
        float* row = out + (size_t)ch * CH_STRIDE + (size_t)d * PLANE + h * OUT_S;
        for (int i = lane; i < OUT_S; i += 32) row[i] = bv;
    } else {
        int idx = (b - U_BLOCKS - DHROW_BLOCKS) * 256 + tid;
        int ch  = idx >> 12;
        int rem = idx & 4095;
        int d   = rem >> 6;
        int h   = rem & 63;
        float bv = __ldg(&bias[ch & 31]);
        float2* p = (float2*)(out + (size_t)ch * CH_STRIDE
                              + (size_t)d * PLANE + h * OUT_S + 64);
        *p = make_float2(bv, bv);
    }
}

// ---------------------------------------------------------------------------
__device__ __forceinline__ void cp4_zfill(uint32_t saddr, const float* g, int ok) {
    asm volatile("cp.async.ca.shared.global [%0], [%1], 4, %2;"
                 :: "r"(saddr), "l"(g), "r"(ok ? 4 : 0) : "memory");
}
__device__ __forceinline__ void cp16(uint32_t saddr, const float4* g) {
    asm volatile("cp.async.cg.shared.global [%0], [%1], 16;"
                 :: "r"(saddr), "l"(g) : "memory");
}
__device__ __forceinline__ void cp_commit() {
    asm volatile("cp.async.commit_group;" ::: "memory");
}
template <int N>
__device__ __forceinline__ void cp_wait() {
    asm volatile("cp.async.wait_group %0;" :: "n"(N) : "memory");
}

// ---------------------------------------------------------------------------
// Block = 256 threads. CTA tile: 2 zd x 8 h x 4 w (z coords) = 8 hw-tiles.
// Multiply decode: tp = tid&3 (tile pair), cog = (tid>>2)&3 (co base 8*cog),
// pt = tid>>4 (Winograd point).
// acc[zd 2][e 2][co-pair 4] f32x2 = 32 regs.
// Grid (8,4,32) = 1024 CTAs; 2 co-resident per SM.
// ---------------------------------------------------------------------------
__global__ void __launch_bounds__(256, 2)
conv_wino_kernel(const float* __restrict__ x,
                 const float* __restrict__ bias,
                 float* __restrict__ out) {
    extern __shared__ __align__(16) char smem[];
    uint32_t sb;
    asm("{ .reg .u64 t; cvta.to.shared.u64 t, %1; cvt.u32.u64 %0, t; }"
        : "=r"(sb) : "l"(smem));

    const int tid = threadIdx.x;
    const int tp  = tid & 3;
    const int cog = (tid >> 2) & 3;
    const int pt  = tid >> 4;                 // 0..15

    const int tw = blockIdx.x;                // 0..7 (w-tile of 4)
    const int th = blockIdx.y;                // 0..3 (h-tile of 8)
    const int nz = blockIdx.z;                // 0..31
    const int n  = nz >> 4;
    const int td = nz & 15;
    const int zd0 = td * 2, zh0 = th * 8, zw0 = tw * 4;

    const float* xn = x + (size_t)n * (64 * 32768);
    float* Vs = (float*)(smem + SM_V);

    auto issue_chunk = [&](int cc, int buf) {
        // x halo: 4ci x [4][10][6] = 960 floats
        uint32_t sx = sb + buf * X_BYTES;
#pragma unroll
        for (int j = 0; j < 4; ++j) {
            int i = tid + j * 256;
            if (i < 960) {
                int ci = i / 240;
                int r  = i - ci * 240;
                int dd = r / 60;
                int r2 = r - dd * 60;
                int hh = r2 / 6;
                int ww = r2 - hh * 6;
                int gd = zd0 - 1 + dd;
                int gh = zh0 - 1 + hh;
                int gw = zw0 - 1 + ww;
                int ok = (gd >= 0 && gd < 32 && gh >= 0 && gh < 32 &&
                          gw >= 0 && gw < 32);
                const float* g = xn + (((size_t)(cc * CIC + ci) * 32 + (gd & 31))
                                       * 32 + (gh & 31)) * 32 + (gw & 31);
                cp4_zfill(sx + i * 4, g, ok);
            }
        }
        // U chunk: 3kd x 4ci x 16pt x 36 = 1728 float4
        uint32_t su = sb + SM_U0 + buf * U_BYTES;
#pragma unroll
        for (int j = 0; j < 7; ++j) {
            int i = tid + j * 256;
            if (i < 1728) {
                int kd = i / 576;
                int r  = i - kd * 576;
                const float4* src = (const float4*)
                    (g_U + (kd * 64 + cc * CIC) * (16 * 36)) + r;
                cp16(su + (kd * 576 + r) * 16, src);
            }
        }
        cp_commit();
    };

    // acc[zd][e][j]: tile 2tp+e, co pair {8cog+2j, 8cog+2j+1}
    unsigned long long acc[2][2][4];
#pragma unroll
    for (int a = 0; a < 2; ++a)
#pragma unroll
    for (int e = 0; e < 2; ++e)
#pragma unroll
    for (int j = 0; j < 4; ++j) acc[a][e][j] = 0ull;

    issue_chunk(0, 0);

#pragma unroll 1
    for (int cc = 0; cc < NCHUNK; ++cc) {
        const int buf = cc & 1;
        if (cc + 1 < NCHUNK) {
            issue_chunk(cc + 1, buf ^ 1);
            cp_wait<1>();
        } else {
            cp_wait<0>();
        }
        __syncthreads();

        // ---- build V = B^T d B : 128 units (dd 4, ci 4, tile 8) ----
        if (tid < 128) {
            int t  = tid & 7;                 // t = a*2 + b
            int ci = (tid >> 3) & 3;
            int dd = tid >> 5;                // 0..3
            int a  = t >> 1, b2 = t & 1;
            const float* dp = (const float*)(smem + buf * X_BYTES)
                            + ci * 240 + dd * 60 + (2 * a) * 6 + 2 * b2;
            float rt[4][4];
#pragma unroll
            for (int i = 0; i < 4; ++i) {
                float d0 = dp[i * 6 + 0], d1 = dp[i * 6 + 1];
                float d2 = dp[i * 6 + 2], d3 = dp[i * 6 + 3];
                rt[i][0] = d0 - d2;
                rt[i][1] = d1 + d2;
                rt[i][2] = d2 - d1;
                rt[i][3] = d1 - d3;
            }
            float* vd = Vs + (dd * 4 + ci) * VCI + t;
#pragma unroll
            for (int q = 0; q < 4; ++q) {
                vd[(0 * 4 + q) * 8] = rt[0][q] - rt[2][q];
                vd[(1 * 4 + q) * 8] = rt[1][q] + rt[2][q];
                vd[(2 * 4 + q) * 8] = rt[2][q] - rt[1][q];
                vd[(3 * 4 + q) * 8] = rt[1][q] - rt[3][q];
            }
        }
        __syncthreads();

        // ---- multiply: M[zd] += V[zd+kd] * U[kd] ----
        {
            const float* Ub = (const float*)(smem + SM_U0 + buf * U_BYTES);
#pragma unroll 1
            for (int ci = 0; ci < CIC; ++ci) {
                unsigned long long xv[4][2];
#pragma unroll
                for (int dd = 0; dd < 4; ++dd) {
                    float2 f = *(const float2*)
                        (Vs + (dd * 4 + ci) * VCI + pt * 8 + 2 * tp);
                    asm("mov.b64 %0, {%1, %1};" : "=l"(xv[dd][0]) : "f"(f.x));
                    asm("mov.b64 %0, {%1, %1};" : "=l"(xv[dd][1]) : "f"(f.y));
                }
#pragma unroll
                for (int kd = 0; kd < 3; ++kd) {
                    const float* up = Ub + ((kd * 4 + ci) * 16 + pt) * 36
                                    + 8 * cog;
                    ulonglong2 w0 = *(const ulonglong2*)up;
                    ulonglong2 w1 = *(const ulonglong2*)(up + 4);
#pragma unroll
                    for (int zd = 0; zd < 2; ++zd) {
#pragma unroll
                        for (int e = 0; e < 2; ++e) {
                            unsigned long long xvv = xv[zd + kd][e];
                            asm("fma.rn.f32x2 %0, %1, %2, %0;"
                                : "+l"(acc[zd][e][0]) : "l"(xvv), "l"(w0.x));
                            asm("fma.rn.f32x2 %0, %1, %2, %0;"
                                : "+l"(acc[zd][e][1]) : "l"(xvv), "l"(w0.y));
                            asm("fma.rn.f32x2 %0, %1, %2, %0;"
                                : "+l"(acc[zd][e][2]) : "l"(xvv), "l"(w1.x));
                            asm("fma.rn.f32x2 %0, %1, %2, %0;"
                                : "+l"(acc[zd][e][3]) : "l"(xvv), "l"(w1.y));
                        }
                    }
                }
            }
        }
        __syncthreads();
    }

    // ---- output: per zd: stage M, transform Y = A^T M A, store cubes ----
    float* Msm = Vs;                       // [pt][33 co][8 t]
    const int t2  = tid & 7;
    const int co2 = (tid >> 3) & 31;
    const float bvv = __ldg(&bias[co2]);
    const int a2 = t2 >> 1, b2 = t2 & 1;

#pragma unroll 1
    for (int zd = 0; zd < 2; ++zd) {
#pragma unroll
        for (int e = 0; e < 2; ++e) {
#pragma unroll
            for (int j = 0; j < 4; ++j) {
                float2 v;
                asm("mov.b64 {%0, %1}, %2;"
                    : "=f"(v.x), "=f"(v.y) : "l"(acc[zd][e][j]));
                int co = 8 * cog + 2 * j;
                int t  = 2 * tp + e;
                Msm[(pt * 33 + co)     * 8 + t] = v.x;
                Msm[(pt * 33 + co + 1) * 8 + t] = v.y;
            }
        }
        __syncthreads();

        float m[16];
#pragma unroll
        for (int p = 0; p < 16; ++p)
            m[p] = Msm[(p * 33 + co2) * 8 + t2];
        float tq0[4], tq1[4];
#pragma unroll
        for (int p = 0; p < 4; ++p) {
            tq0[p] = m[4 * p] + m[4 * p + 1] + m[4 * p + 2];
            tq1[p] = m[4 * p + 1] - m[4 * p + 2] - m[4 * p + 3];
        }
        float Y[2][2];
        Y[0][0] = tq0[0] + tq0[1] + tq0[2];
        Y[0][1] = tq1[0] + tq1[1] + tq1[2];
        Y[1][0] = tq0[1] - tq0[2] - tq0[3];
        Y[1][1] = tq1[1] - tq1[2] - tq1[3];

        const int zg = zd0 + zd;
#pragma unroll
        for (int i = 0; i < 2; ++i) {
#pragma unroll
            for (int j = 0; j < 2; ++j) {
                const int hg = zh0 + 2 * a2 + i;
                const int wg = zw0 + 2 * b2 + j;
                float* base = out + (size_t)(n * 32 + co2) * CH_STRIDE
                            + (size_t)(2 * zg) * PLANE
                            + (2 * hg) * OUT_S + 2 * wg;
                float2 bb = make_float2(bvv, bvv);
                float2 bc = make_float2(bvv, Y[i][j] + bvv);
                *(float2*)(base)                 = bb;
                *(float2*)(base + OUT_S)         = bb;
                *(float2*)(base + PLANE)         = bb;
                *(float2*)(base + PLANE + OUT_S) = bc;
            }
        }
        __syncthreads();
    }
}

// ---------------------------------------------------------------------------
extern "C" void kernel_launch(void* const* d_in, const int* in_sizes, int n_in,
                              void* d_out, int out_size) {
    const float* x = nullptr;
    const float* w = nullptr;
    const float* b = nullptr;
    for (int i = 0; i < n_in; ++i) {
        if (in_sizes[i] == 4194304)    x = (const float*)d_in[i];
        else if (in_sizes[i] == 55296) w = (const float*)d_in[i];
        else if (in_sizes[i] == 32)    b = (const float*)d_in[i];
    }
    float* out = (float*)d_out;

    cudaFuncSetAttribute(conv_wino_kernel,
                         cudaFuncAttributeMaxDynamicSharedMemorySize, SM_TOTAL);

    prep_kernel<<<PREP_BLOCKS, 256>>>(w, b, out);

    dim3 grid(8, 4, 32);   // 1024 CTAs, 2 co-resident per SM
    conv_wino_kernel<<<grid, 256, SM_TOTAL>>>(x, b, out);
}